// round 9
// baseline (speedup 1.0000x reference)
#include <cuda_runtime.h>
#include <stdint.h>
#include <math.h>

// Fixed shapes
#define CDIM   64
#define HW     4096                 // 64*64
#define KCODES 512
#define NPTS   131072               // 32*4096
#define NQ     (NPTS*CDIM)          // 8388608
// Output layout: [loss(1) | quantized(NQ) | perplexity(1) | indices(NPTS)]
#define QOFF   1
#define POFF   (1+NQ)
#define IOFF   (2+NQ)

#define TPB      256                // 8 warps
#define PTS_WARP 16
#define PTS_CTA  128
#define NCTA     (NPTS/PTS_CTA)     // 1024
#define NCT      (KCODES/8)         // 64 code tiles of 8

__device__ float g_Bfrag[NCT*32*32];    // [ct][lane][32]: 16 hi + 16 lo, frag order
__device__ float g_se2[KCODES];
__device__ int   g_counts[KCODES];
__device__ float g_loss;

__device__ __forceinline__ unsigned f2tf32(float v) {
    unsigned r;
    asm("cvt.rna.tf32.f32 %0, %1;" : "=r"(r) : "f"(v));
    return r;
}

#define MMA_TF32(d0,d1,d2,d3, a0,a1,a2,a3, b0,b1)                              \
    asm("mma.sync.aligned.m16n8k8.row.col.f32.tf32.tf32.f32 "                  \
        "{%0,%1,%2,%3}, {%4,%5,%6,%7}, {%8,%9}, {%0,%1,%2,%3};"                \
        : "+f"(d0), "+f"(d1), "+f"(d2), "+f"(d3)                               \
        : "r"(a0), "r"(a1), "r"(a2), "r"(a3), "r"(b0), "r"(b1))

// ---------------- prep: pack B fragments (tf32 hi/lo), se2, zero accums ------
__global__ void __launch_bounds__(256)
vq_prep(const float* __restrict__ emb) {
    int id = blockIdx.x * 256 + threadIdx.x;
    if (id < NCT*32*16) {
        int ct   = id >> 9;
        int lane = (id >> 4) & 31;
        int jh   = id & 15;
        int ks = jh >> 1, rg = jh & 1;
        int chan = ks*8 + (lane & 3) + rg*4;
        int code = ct*8 + (lane >> 2);
        float v  = emb[chan*KCODES + code];
        unsigned hi = f2tf32(v);
        float lo = v - __uint_as_float(hi);
        unsigned lo32 = f2tf32(lo);
        g_Bfrag[ct*1024 + lane*32 + jh]      = __uint_as_float(hi);
        g_Bfrag[ct*1024 + lane*32 + 16 + jh] = __uint_as_float(lo32);
    } else if (id < NCT*32*16 + KCODES) {
        int k = id - NCT*32*16;
        float s = 0.0f;
        #pragma unroll 8
        for (int c = 0; c < CDIM; c++) {
            float v = emb[c*KCODES + k];
            s = fmaf(v, v, s);
        }
        g_se2[k] = s;
        g_counts[k] = 0;
        if (k == 0) g_loss = 0.0f;
    }
}

// ---------------- main: distances + argmin (no quantized write) --------------
__global__ void __launch_bounds__(TPB, 2)
vq_main(const float* __restrict__ x, float* __restrict__ out) {
    __shared__ float sse2[KCODES];
    __shared__ int   shist[KCODES];
    __shared__ float wred[8];

    const int tid  = threadIdx.x;
    const int warp = tid >> 5;
    const int lane = tid & 31;
    const int g    = lane >> 2;     // group (row within tile)
    const int t    = lane & 3;      // thread-in-group

    sse2[tid]       = g_se2[tid];
    sse2[tid + TPB] = g_se2[tid + TPB];
    shist[tid] = 0; shist[tid + TPB] = 0;

    // ---- load this warp's 16 points as tf32-split A fragments --------------
    const int p0w = blockIdx.x * PTS_CTA + warp * PTS_WARP;
    const int b   = p0w >> 12;
    const int hw  = p0w & (HW - 1);
    const float* Base = x + (size_t)b * CDIM * HW + hw;

    unsigned ahi[32], alo[32];
    float zsq0 = 0.0f, zsq1 = 0.0f;
    #pragma unroll
    for (int ks = 0; ks < 8; ks++) {
        int c0 = ks*8 + t;
        float v0 = Base[g     + (size_t)c0      * HW];
        float v1 = Base[g + 8 + (size_t)c0      * HW];
        float v2 = Base[g     + (size_t)(c0+4)  * HW];
        float v3 = Base[g + 8 + (size_t)(c0+4)  * HW];
        zsq0 = fmaf(v0, v0, zsq0); zsq0 = fmaf(v2, v2, zsq0);
        zsq1 = fmaf(v1, v1, zsq1); zsq1 = fmaf(v3, v3, zsq1);
        unsigned h0 = f2tf32(v0), h1 = f2tf32(v1), h2 = f2tf32(v2), h3 = f2tf32(v3);
        ahi[ks*4+0] = h0; ahi[ks*4+1] = h1; ahi[ks*4+2] = h2; ahi[ks*4+3] = h3;
        alo[ks*4+0] = f2tf32(v0 - __uint_as_float(h0));
        alo[ks*4+1] = f2tf32(v1 - __uint_as_float(h1));
        alo[ks*4+2] = f2tf32(v2 - __uint_as_float(h2));
        alo[ks*4+3] = f2tf32(v3 - __uint_as_float(h3));
    }
    __syncthreads();

    // ---- 64 code tiles; 3 independent MMA chains per tile ------------------
    float best0 = 3.4e38f, best1 = 3.4e38f;
    int   bi0 = 0, bi1 = 0;
    const float4* Bp = (const float4*)g_Bfrag + (size_t)lane * 8;

    #pragma unroll 1
    for (int ct = 0; ct < NCT; ct++) {
        float4 Bf[8];
        #pragma unroll
        for (int m = 0; m < 8; m++) Bf[m] = Bp[ct*256 + m];

        float hh0=0.f,hh1=0.f,hh2=0.f,hh3=0.f;
        float hl0=0.f,hl1=0.f,hl2=0.f,hl3=0.f;
        float lh0=0.f,lh1=0.f,lh2=0.f,lh3=0.f;
        #pragma unroll
        for (int ks = 0; ks < 8; ks++) {
            unsigned bh0, bh1, bl0, bl1;
            if ((ks & 1) == 0) {
                bh0 = __float_as_uint(Bf[ks>>1].x); bh1 = __float_as_uint(Bf[ks>>1].y);
                bl0 = __float_as_uint(Bf[4+(ks>>1)].x); bl1 = __float_as_uint(Bf[4+(ks>>1)].y);
            } else {
                bh0 = __float_as_uint(Bf[ks>>1].z); bh1 = __float_as_uint(Bf[ks>>1].w);
                bl0 = __float_as_uint(Bf[4+(ks>>1)].z); bl1 = __float_as_uint(Bf[4+(ks>>1)].w);
            }
            MMA_TF32(hh0,hh1,hh2,hh3, ahi[ks*4+0],ahi[ks*4+1],ahi[ks*4+2],ahi[ks*4+3], bh0,bh1);
            MMA_TF32(hl0,hl1,hl2,hl3, ahi[ks*4+0],ahi[ks*4+1],ahi[ks*4+2],ahi[ks*4+3], bl0,bl1);
            MMA_TF32(lh0,lh1,lh2,lh3, alo[ks*4+0],alo[ks*4+1],alo[ks*4+2],alo[ks*4+3], bh0,bh1);
        }
        float d0 = (hh0 + hl0) + lh0;
        float d1 = (hh1 + hl1) + lh1;
        float d2 = (hh2 + hl2) + lh2;
        float d3 = (hh3 + hl3) + lh3;

        // dist = ||e||^2 - 2*dot (||z||^2 constant per row)
        int col = ct*8 + 2*t;
        float s0 = sse2[col], s1 = sse2[col+1];
        float q0 = fmaf(-2.0f, d0, s0);
        float q1 = fmaf(-2.0f, d1, s1);
        float q2 = fmaf(-2.0f, d2, s0);
        float q3 = fmaf(-2.0f, d3, s1);
        if (q0 < best0 || (q0 == best0 && col   < bi0)) { best0 = q0; bi0 = col;   }
        if (q1 < best0 || (q1 == best0 && col+1 < bi0)) { best0 = q1; bi0 = col+1; }
        if (q2 < best1 || (q2 == best1 && col   < bi1)) { best1 = q2; bi1 = col;   }
        if (q3 < best1 || (q3 == best1 && col+1 < bi1)) { best1 = q3; bi1 = col+1; }
    }

    // ---- reduce across the 4 threads of each group (full butterfly) --------
    #pragma unroll
    for (int off = 1; off <= 2; off <<= 1) {
        float ob0 = __shfl_xor_sync(0xffffffffu, best0, off);
        int   oi0 = __shfl_xor_sync(0xffffffffu, bi0,   off);
        float ob1 = __shfl_xor_sync(0xffffffffu, best1, off);
        int   oi1 = __shfl_xor_sync(0xffffffffu, bi1,   off);
        float oz0 = __shfl_xor_sync(0xffffffffu, zsq0,  off);
        float oz1 = __shfl_xor_sync(0xffffffffu, zsq1,  off);
        if (ob0 < best0 || (ob0 == best0 && oi0 < bi0)) { best0 = ob0; bi0 = oi0; }
        if (ob1 < best1 || (ob1 == best1 && oi1 < bi1)) { best1 = ob1; bi1 = oi1; }
        zsq0 += oz0; zsq1 += oz1;
    }

    // ---- emit indices, hist, loss partial ----------------------------------
    float lsum = 0.0f;
    if (t == 0) {
        out[IOFF + p0w + g]     = (float)bi0;
        out[IOFF + p0w + g + 8] = (float)bi1;
        atomicAdd(&shist[bi0], 1);
        atomicAdd(&shist[bi1], 1);
        lsum = (best0 + zsq0) + (best1 + zsq1);   // true min squared distances
    }
    #pragma unroll
    for (int o = 16; o > 0; o >>= 1)
        lsum += __shfl_down_sync(0xffffffffu, lsum, o);
    if (lane == 0) wred[warp] = lsum;

    __syncthreads();
    // flush hist + loss
    { int h = shist[tid];       if (h) atomicAdd(&g_counts[tid], h);
      h     = shist[tid + TPB]; if (h) atomicAdd(&g_counts[tid + TPB], h); }
    if (tid < 8) {
        float v = wred[tid];
        #pragma unroll
        for (int o = 4; o > 0; o >>= 1)
            v += __shfl_down_sync(0xffu, v, o);
        if (tid == 0) atomicAdd(&g_loss, v);
    }
}

// ---------------- gather: quantized output from indices ----------------------
#define GCTA 128
#define GPTS (NPTS/GCTA)   // 1024 points per CTA
__global__ void __launch_bounds__(256)
vq_gather(const float* __restrict__ emb, float* __restrict__ out) {
    extern __shared__ float sE[];   // [64][512]
    const int tid = threadIdx.x;
    {
        const float4* e4 = (const float4*)emb;
        float4* s4 = (float4*)sE;
        #pragma unroll
        for (int i = tid; i < CDIM*KCODES/4; i += 256) s4[i] = e4[i];
    }
    __syncthreads();
    const int P0 = blockIdx.x * GPTS;
    #pragma unroll 1
    for (int pp = tid; pp < GPTS; pp += 256) {
        const int p  = P0 + pp;
        const int b  = p >> 12;
        const int hw = p & (HW - 1);
        const int bi = (int)out[IOFF + p];
        float* oq = out + QOFF + (size_t)b * CDIM * HW + hw;
        #pragma unroll 8
        for (int c = 0; c < CDIM; c++)
            oq[(size_t)c * HW] = sE[c * KCODES + bi];
    }
}

// ---------------- finalize ---------------------------------------------------
__global__ void __launch_bounds__(KCODES)
vq_final(float* __restrict__ out) {
    __shared__ float ws[16];
    const int tt = threadIdx.x;   // 512
    float pr = (float)g_counts[tt] * (1.0f / (float)NPTS);
    float v  = pr * logf(pr + 1e-10f);
    #pragma unroll
    for (int o = 16; o > 0; o >>= 1)
        v += __shfl_down_sync(0xffffffffu, v, o);
    if ((tt & 31) == 0) ws[tt >> 5] = v;
    __syncthreads();
    if (tt < 16) {
        float s = ws[tt];
        #pragma unroll
        for (int o = 8; o > 0; o >>= 1)
            s += __shfl_down_sync(0xffffu, s, o);
        if (tt == 0) {
            // loss = q_latent + 0.25*e_latent; both equal mean((q-z)^2)
            out[0]    = g_loss * (1.25f / (float)NQ);
            out[POFF] = expf(-s);
        }
    }
}

extern "C" void kernel_launch(void* const* d_in, const int* in_sizes, int n_in,
                              void* d_out, int out_size) {
    const float* x   = (const float*)d_in[0];
    const float* emb = (const float*)d_in[1];
    float* out = (float*)d_out;

    cudaFuncSetAttribute(vq_gather, cudaFuncAttributeMaxDynamicSharedMemorySize,
                         CDIM*KCODES*4);

    vq_prep<<<(NCT*32*16 + KCODES + 255)/256, 256>>>(emb);
    vq_main<<<NCTA, TPB>>>(x, out);
    vq_gather<<<GCTA, 256, CDIM*KCODES*4>>>(emb, out);
    vq_final<<<1, KCODES>>>(out);
}

// round 10
// speedup vs baseline: 4.0573x; 4.0573x over previous
#include <cuda_runtime.h>
#include <stdint.h>
#include <math.h>

// Fixed shapes
#define CDIM   64
#define HW     4096                 // 64*64
#define KCODES 512
#define NPTS   131072               // 32*4096
#define NQ     (NPTS*CDIM)          // 8388608
// Output layout: [loss(1) | quantized(NQ) | perplexity(1) | indices(NPTS)]
#define QOFF   1
#define POFF   (1+NQ)
#define IOFF   (2+NQ)

#define TPB      256                // 8 warps
#define PTS_WARP 16
#define PTS_CTA  128
#define NCTA     (NPTS/PTS_CTA)     // 1024
#define NCT      (KCODES/8)         // 64 code tiles of 8

// [ct][m(0..7)][lane] float4 fragments; +1 tile of padding for prefetch overrun
__device__ float g_Bfrag[(NCT+1)*8*32*4];
__device__ float g_se2[KCODES];
__device__ int   g_counts[KCODES];
__device__ float g_loss;

__device__ __forceinline__ unsigned f2tf32(float v) {
    unsigned r;
    asm("cvt.rna.tf32.f32 %0, %1;" : "=r"(r) : "f"(v));
    return r;
}

#define MMA_TF32(d0,d1,d2,d3, a0,a1,a2,a3, b0,b1)                              \
    asm("mma.sync.aligned.m16n8k8.row.col.f32.tf32.tf32.f32 "                  \
        "{%0,%1,%2,%3}, {%4,%5,%6,%7}, {%8,%9}, {%0,%1,%2,%3};"                \
        : "+f"(d0), "+f"(d1), "+f"(d2), "+f"(d3)                               \
        : "r"(a0), "r"(a1), "r"(a2), "r"(a3), "r"(b0), "r"(b1))

// ---------------- prep: pack B fragments (tf32 hi/lo), se2, zero accums ------
__global__ void __launch_bounds__(256)
vq_prep(const float* __restrict__ emb) {
    int id = blockIdx.x * 256 + threadIdx.x;
    if (id < NCT*32*16) {
        int ct   = id >> 9;
        int lane = (id >> 4) & 31;
        int jh   = id & 15;
        int ks = jh >> 1, rg = jh & 1;
        int chan = ks*8 + (lane & 3) + rg*4;
        int code = ct*8 + (lane >> 2);
        float v  = emb[chan*KCODES + code];
        unsigned hi = f2tf32(v);
        float lo = v - __uint_as_float(hi);
        unsigned lo32 = f2tf32(lo);
        int m    = jh >> 2;          // fragment float4 index (hi: 0..3)
        int comp = jh & 3;
        g_Bfrag[((ct*8 + m    )*32 + lane)*4 + comp] = __uint_as_float(hi);
        g_Bfrag[((ct*8 + 4 + m)*32 + lane)*4 + comp] = __uint_as_float(lo32);
    } else if (id < NCT*32*16 + KCODES) {
        int k = id - NCT*32*16;
        float s = 0.0f;
        #pragma unroll 8
        for (int c = 0; c < CDIM; c++) {
            float v = emb[c*KCODES + k];
            s = fmaf(v, v, s);
        }
        g_se2[k] = s;
        g_counts[k] = 0;
        if (k == 0) g_loss = 0.0f;
    }
}

// ---------------- main: distances + argmin (no quantized write) --------------

#define PREFETCH(CT, BF)                                                       \
    { _Pragma("unroll")                                                        \
      for (int m = 0; m < 8; m++) BF[m] = Bp[((CT)*8 + m)*32 + lane]; }

#define TILE_BODY(CT, BF)                                                      \
    {                                                                          \
        float hh0=0.f,hh1=0.f,hh2=0.f,hh3=0.f;                                 \
        float hl0=0.f,hl1=0.f,hl2=0.f,hl3=0.f;                                 \
        float lh0=0.f,lh1=0.f,lh2=0.f,lh3=0.f;                                 \
        _Pragma("unroll")                                                      \
        for (int ks = 0; ks < 8; ks++) {                                       \
            unsigned bh0, bh1, bl0, bl1;                                       \
            if ((ks & 1) == 0) {                                               \
                bh0 = __float_as_uint(BF[ks>>1].x);                            \
                bh1 = __float_as_uint(BF[ks>>1].y);                            \
                bl0 = __float_as_uint(BF[4+(ks>>1)].x);                        \
                bl1 = __float_as_uint(BF[4+(ks>>1)].y);                        \
            } else {                                                           \
                bh0 = __float_as_uint(BF[ks>>1].z);                            \
                bh1 = __float_as_uint(BF[ks>>1].w);                            \
                bl0 = __float_as_uint(BF[4+(ks>>1)].z);                        \
                bl1 = __float_as_uint(BF[4+(ks>>1)].w);                        \
            }                                                                  \
            MMA_TF32(hh0,hh1,hh2,hh3,                                          \
                     ahi[ks*4+0],ahi[ks*4+1],ahi[ks*4+2],ahi[ks*4+3], bh0,bh1);\
            MMA_TF32(hl0,hl1,hl2,hl3,                                          \
                     ahi[ks*4+0],ahi[ks*4+1],ahi[ks*4+2],ahi[ks*4+3], bl0,bl1);\
            MMA_TF32(lh0,lh1,lh2,lh3,                                          \
                     alo[ks*4+0],alo[ks*4+1],alo[ks*4+2],alo[ks*4+3], bh0,bh1);\
        }                                                                      \
        float d0 = (hh0 + hl0) + lh0;                                          \
        float d1 = (hh1 + hl1) + lh1;                                          \
        float d2 = (hh2 + hl2) + lh2;                                          \
        float d3 = (hh3 + hl3) + lh3;                                          \
        int col = (CT)*8 + 2*t;                                                \
        float s0 = sse2[col], s1 = sse2[col+1];                                \
        float q0 = fmaf(-2.0f, d0, s0);                                        \
        float q1 = fmaf(-2.0f, d1, s1);                                        \
        float q2 = fmaf(-2.0f, d2, s0);                                        \
        float q3 = fmaf(-2.0f, d3, s1);                                        \
        if (q0 < best0 || (q0 == best0 && col   < bi0)) { best0 = q0; bi0 = col;   } \
        if (q1 < best0 || (q1 == best0 && col+1 < bi0)) { best0 = q1; bi0 = col+1; } \
        if (q2 < best1 || (q2 == best1 && col   < bi1)) { best1 = q2; bi1 = col;   } \
        if (q3 < best1 || (q3 == best1 && col+1 < bi1)) { best1 = q3; bi1 = col+1; } \
    }

__global__ void __launch_bounds__(TPB)
vq_main(const float* __restrict__ x, float* __restrict__ out) {
    __shared__ float sse2[KCODES];
    __shared__ int   shist[KCODES];
    __shared__ float wred[8];

    const int tid  = threadIdx.x;
    const int warp = tid >> 5;
    const int lane = tid & 31;
    const int g    = lane >> 2;     // group (row within tile)
    const int t    = lane & 3;      // thread-in-group

    sse2[tid]       = g_se2[tid];
    sse2[tid + TPB] = g_se2[tid + TPB];
    shist[tid] = 0; shist[tid + TPB] = 0;

    // ---- load this warp's 16 points as tf32-split A fragments --------------
    const int p0w = blockIdx.x * PTS_CTA + warp * PTS_WARP;
    const int b   = p0w >> 12;
    const int hw  = p0w & (HW - 1);
    const float* Base = x + (size_t)b * CDIM * HW + hw;

    unsigned ahi[32], alo[32];
    float zsq0 = 0.0f, zsq1 = 0.0f;
    #pragma unroll
    for (int ks = 0; ks < 8; ks++) {
        int c0 = ks*8 + t;
        float v0 = Base[g     + (size_t)c0      * HW];
        float v1 = Base[g + 8 + (size_t)c0      * HW];
        float v2 = Base[g     + (size_t)(c0+4)  * HW];
        float v3 = Base[g + 8 + (size_t)(c0+4)  * HW];
        zsq0 = fmaf(v0, v0, zsq0); zsq0 = fmaf(v2, v2, zsq0);
        zsq1 = fmaf(v1, v1, zsq1); zsq1 = fmaf(v3, v3, zsq1);
        unsigned h0 = f2tf32(v0), h1 = f2tf32(v1), h2 = f2tf32(v2), h3 = f2tf32(v3);
        ahi[ks*4+0] = h0; ahi[ks*4+1] = h1; ahi[ks*4+2] = h2; ahi[ks*4+3] = h3;
        alo[ks*4+0] = f2tf32(v0 - __uint_as_float(h0));
        alo[ks*4+1] = f2tf32(v1 - __uint_as_float(h1));
        alo[ks*4+2] = f2tf32(v2 - __uint_as_float(h2));
        alo[ks*4+3] = f2tf32(v3 - __uint_as_float(h3));
    }
    __syncthreads();

    // ---- 64 code tiles; coalesced fragment loads, double-buffered ----------
    float best0 = 3.4e38f, best1 = 3.4e38f;
    int   bi0 = 0, bi1 = 0;
    const float4* Bp = (const float4*)g_Bfrag;

    float4 B0[8], B1[8];
    PREFETCH(0, B0);
    #pragma unroll 1
    for (int ct = 0; ct < NCT; ct += 2) {
        PREFETCH(ct+1, B1);
        TILE_BODY(ct, B0);
        PREFETCH(ct+2, B0);       // ct=62 -> tile 64 = padding, safe
        TILE_BODY(ct+1, B1);
    }

    // ---- reduce across the 4 threads of each group (full butterfly) --------
    #pragma unroll
    for (int off = 1; off <= 2; off <<= 1) {
        float ob0 = __shfl_xor_sync(0xffffffffu, best0, off);
        int   oi0 = __shfl_xor_sync(0xffffffffu, bi0,   off);
        float ob1 = __shfl_xor_sync(0xffffffffu, best1, off);
        int   oi1 = __shfl_xor_sync(0xffffffffu, bi1,   off);
        float oz0 = __shfl_xor_sync(0xffffffffu, zsq0,  off);
        float oz1 = __shfl_xor_sync(0xffffffffu, zsq1,  off);
        if (ob0 < best0 || (ob0 == best0 && oi0 < bi0)) { best0 = ob0; bi0 = oi0; }
        if (ob1 < best1 || (ob1 == best1 && oi1 < bi1)) { best1 = ob1; bi1 = oi1; }
        zsq0 += oz0; zsq1 += oz1;
    }

    // ---- emit indices, hist, loss partial ----------------------------------
    float lsum = 0.0f;
    if (t == 0) {
        out[IOFF + p0w + g]     = (float)bi0;
        out[IOFF + p0w + g + 8] = (float)bi1;
        atomicAdd(&shist[bi0], 1);
        atomicAdd(&shist[bi1], 1);
        lsum = (best0 + zsq0) + (best1 + zsq1);   // true min squared distances
    }
    #pragma unroll
    for (int o = 16; o > 0; o >>= 1)
        lsum += __shfl_down_sync(0xffffffffu, lsum, o);
    if (lane == 0) wred[warp] = lsum;

    __syncthreads();
    // flush hist + loss
    { int h = shist[tid];       if (h) atomicAdd(&g_counts[tid], h);
      h     = shist[tid + TPB]; if (h) atomicAdd(&g_counts[tid + TPB], h); }
    if (tid < 8) {
        float v = wred[tid];
        #pragma unroll
        for (int o = 4; o > 0; o >>= 1)
            v += __shfl_down_sync(0xffu, v, o);
        if (tid == 0) atomicAdd(&g_loss, v);
    }
}

// ---------------- gather: quantized output from indices ----------------------
#define GCTA 128
#define GPTS (NPTS/GCTA)   // 1024 points per CTA
__global__ void __launch_bounds__(256)
vq_gather(const float* __restrict__ emb, float* __restrict__ out) {
    extern __shared__ float sE[];   // [64][512]
    const int tid = threadIdx.x;
    {
        const float4* e4 = (const float4*)emb;
        float4* s4 = (float4*)sE;
        #pragma unroll
        for (int i = tid; i < CDIM*KCODES/4; i += 256) s4[i] = e4[i];
    }
    __syncthreads();
    const int P0 = blockIdx.x * GPTS;
    #pragma unroll 1
    for (int pp = tid; pp < GPTS; pp += 256) {
        const int p  = P0 + pp;
        const int b  = p >> 12;
        const int hw = p & (HW - 1);
        const int bi = (int)out[IOFF + p];
        float* oq = out + QOFF + (size_t)b * CDIM * HW + hw;
        #pragma unroll 8
        for (int c = 0; c < CDIM; c++)
            oq[(size_t)c * HW] = sE[c * KCODES + bi];
    }
}

// ---------------- finalize ---------------------------------------------------
__global__ void __launch_bounds__(KCODES)
vq_final(float* __restrict__ out) {
    __shared__ float ws[16];
    const int tt = threadIdx.x;   // 512
    float pr = (float)g_counts[tt] * (1.0f / (float)NPTS);
    float v  = pr * logf(pr + 1e-10f);
    #pragma unroll
    for (int o = 16; o > 0; o >>= 1)
        v += __shfl_down_sync(0xffffffffu, v, o);
    if ((tt & 31) == 0) ws[tt >> 5] = v;
    __syncthreads();
    if (tt < 16) {
        float s = ws[tt];
        #pragma unroll
        for (int o = 8; o > 0; o >>= 1)
            s += __shfl_down_sync(0xffffu, s, o);
        if (tt == 0) {
            // loss = q_latent + 0.25*e_latent; both equal mean((q-z)^2)
            out[0]    = g_loss * (1.25f / (float)NQ);
            out[POFF] = expf(-s);
        }
    }
}

extern "C" void kernel_launch(void* const* d_in, const int* in_sizes, int n_in,
                              void* d_out, int out_size) {
    const float* x   = (const float*)d_in[0];
    const float* emb = (const float*)d_in[1];
    float* out = (float*)d_out;

    cudaFuncSetAttribute(vq_gather, cudaFuncAttributeMaxDynamicSharedMemorySize,
                         CDIM*KCODES*4);

    vq_prep<<<(NCT*32*16 + KCODES + 255)/256, 256>>>(emb);
    vq_main<<<NCTA, TPB>>>(x, out);
    vq_gather<<<GCTA, 256, CDIM*KCODES*4>>>(emb, out);
    vq_final<<<1, KCODES>>>(out);
}